// round 4
// baseline (speedup 1.0000x reference)
#include <cuda_runtime.h>
#include <math.h>

// Problem constants
#define NTOK   65536     // 32*2048 tokens
#define POSN   65536     // 32*2048 spatial positions (h=32, w=2048)
#define SCALE  0.35355339059327373f   // (64/8)^-0.5

// Scratch (allocation-free rule: device globals)
__device__ float g_G  [4194304];    // gelu output, flat [t*64+c] == CHW [c][h][w]
__device__ float g_QKV[48 * 65536]; // [j][pos]
__device__ float g_OB [16 * 65536]; // [m][pos]
__device__ float g_P  [4194304];    // proj output, flat (same dual-view)

__device__ __forceinline__ float gelu_exact(float h) {
    return 0.5f * h * (1.0f + erff(h * 0.70710678118654752f));
}

// ---------------------------------------------------------------------------
// K1: fc1 (768->64) + 8x pointwise 64x64 conv layers (+skip over L6,L7) + GELU
// thread-per-token, 128 threads/block, 512 blocks.
// smem (floats): bufA@0 (128*65=8320), bufB@8320 (8320), wbuf@16640 (4096), bias@20736 (64)
// phase-1 aliases: xs_s@0 (128*17), w1s@8320 (64*16)
// ---------------------------------------------------------------------------
__global__ __launch_bounds__(128) void k_fc1_conv(
    const float* __restrict__ x, const float* __restrict__ fc1_w,
    const float* __restrict__ fc1_b, const float* __restrict__ conv_w,
    const float* __restrict__ conv_b)
{
    extern __shared__ float sm[];
    float* bufA = sm;
    float* bufB = sm + 8320;
    float* wbuf = sm + 16640;
    float* bias = sm + 20736;

    const int tid = threadIdx.x;
    const int t0  = blockIdx.x * 128;

    if (tid < 64) bias[tid] = fc1_b[tid];

    float acc[64];
#pragma unroll
    for (int c = 0; c < 64; c++) acc[c] = 0.f;

    const float* xrow = x + (size_t)t0 * 768;
    for (int kb = 0; kb < 768; kb += 16) {
        __syncthreads();
        // stage x tile [128 tok][16 k], stride 17 (conflict-free row reads)
        for (int i = tid; i < 2048; i += 128) {
            int tt = i >> 4, kk = i & 15;
            sm[tt * 17 + kk] = xrow[tt * 768 + kb + kk];
        }
        // stage w1s[c][kk]
        for (int i = tid; i < 1024; i += 128) {
            int c = i >> 4, kk = i & 15;
            sm[8320 + i] = fc1_w[c * 768 + kb + kk];
        }
        __syncthreads();
        float xr[16];
#pragma unroll
        for (int kk = 0; kk < 16; kk++) xr[kk] = sm[tid * 17 + kk];
#pragma unroll
        for (int c = 0; c < 64; c++) {
            const float4* wr = (const float4*)(sm + 8320 + c * 16);
            float s = acc[c];
#pragma unroll
            for (int k4 = 0; k4 < 4; k4++) {
                float4 wv = wr[k4];
                s += xr[k4 * 4 + 0] * wv.x;
                s += xr[k4 * 4 + 1] * wv.y;
                s += xr[k4 * 4 + 2] * wv.z;
                s += xr[k4 * 4 + 3] * wv.w;
            }
            acc[c] = s;
        }
    }
    __syncthreads();
#pragma unroll
    for (int c = 0; c < 64; c++) bufA[tid * 65 + c] = acc[c] + bias[c];

    // 8 pointwise conv layers; residual skip from after-L5 to after-L7.
    // L even: bufA->bufB ; L odd: bufB->bufA. Post-L5 result sits in bufA,
    // which is also L7's dst: per-element read-before-write gives the skip.
    for (int L = 0; L < 8; L++) {
        __syncthreads();
        for (int i = tid; i < 4096; i += 128) wbuf[i] = conv_w[L * 4096 + i];
        if (tid < 64) bias[tid] = conv_b[L * 64 + tid];
        __syncthreads();
        float* src = (L & 1) ? bufB : bufA;
        float* dst = (L & 1) ? bufA : bufB;
        float h[64];
#pragma unroll
        for (int c = 0; c < 64; c++) h[c] = src[tid * 65 + c];
        for (int og = 0; og < 8; og++) {
            float a[8];
#pragma unroll
            for (int j = 0; j < 8; j++) a[j] = bias[og * 8 + j];
#pragma unroll
            for (int c4 = 0; c4 < 16; c4++) {
#pragma unroll
                for (int j = 0; j < 8; j++) {
                    float4 wv = *(const float4*)(wbuf + (og * 8 + j) * 64 + c4 * 4);
                    a[j] += h[c4 * 4 + 0] * wv.x + h[c4 * 4 + 1] * wv.y
                          + h[c4 * 4 + 2] * wv.z + h[c4 * 4 + 3] * wv.w;
                }
            }
#pragma unroll
            for (int j = 0; j < 8; j++) {
                float v = a[j];
                if (L == 7) v += dst[tid * 65 + og * 8 + j];   // residual
                dst[tid * 65 + og * 8 + j] = v;
            }
        }
    }
    __syncthreads();

    // GELU + store (final result in bufA)
    float4* gout = (float4*)(g_G + (size_t)(t0 + tid) * 64);
#pragma unroll
    for (int c4 = 0; c4 < 16; c4++) {
        const float* hp = &bufA[tid * 65 + c4 * 4];
        float4 v;
        v.x = gelu_exact(hp[0]);
        v.y = gelu_exact(hp[1]);
        v.z = gelu_exact(hp[2]);
        v.w = gelu_exact(hp[3]);
        gout[c4] = v;
    }
}

// ---------------------------------------------------------------------------
// K2a: qkv pointwise 64->48 over CHW view of g_G
// ---------------------------------------------------------------------------
__global__ __launch_bounds__(256) void k_qkv(
    const float* __restrict__ qkv_w, const float* __restrict__ qkv_b)
{
    __shared__ float wq[64 * 48];   // wq[c][j]
    __shared__ float bq[48];
    const int tid = threadIdx.x;
    for (int i = tid; i < 3072; i += 256) {
        int j = i / 64, c = i % 64;
        wq[c * 48 + j] = qkv_w[i];
    }
    if (tid < 48) bq[tid] = qkv_b[tid];
    __syncthreads();

    const int pos = blockIdx.x * 256 + tid;
    float acc[48];
#pragma unroll
    for (int j = 0; j < 48; j++) acc[j] = bq[j];
    for (int c = 0; c < 64; c++) {
        float xv = g_G[c * POSN + pos];
        const float4* wr = (const float4*)(wq + c * 48);
#pragma unroll
        for (int j4 = 0; j4 < 12; j4++) {
            float4 wv = wr[j4];
            acc[j4 * 4 + 0] += xv * wv.x;
            acc[j4 * 4 + 1] += xv * wv.y;
            acc[j4 * 4 + 2] += xv * wv.z;
            acc[j4 * 4 + 3] += xv * wv.w;
        }
    }
#pragma unroll
    for (int j = 0; j < 48; j++) g_QKV[j * POSN + pos] = acc[j];
}

// ---------------------------------------------------------------------------
// K2b: shift-conv + dep1 3x3 conv on k/v, rpb, 9-way softmax, weighted v-sum
// thread = spatial position, loop over 8 heads
// ---------------------------------------------------------------------------
__global__ __launch_bounds__(256) void k_attn(
    const float* __restrict__ dep1_w, const float* __restrict__ dep_b,
    const float* __restrict__ dep1_b, const float* __restrict__ rpb)
{
    __shared__ float s_w[162];   // dep1_w [o][d]
    __shared__ float s_b0[18];   // dep_b
    __shared__ float s_b1[18];   // dep1_b
    __shared__ float s_r[72];    // rpb [n][s]
    const int tid = threadIdx.x;
    if (tid < 162) s_w[tid] = dep1_w[tid];
    if (tid < 18)  s_b0[tid] = dep_b[tid];
    if (tid < 18)  s_b1[tid] = dep1_b[tid];
    if (tid < 72)  s_r[tid] = rpb[tid];
    __syncthreads();

    const int pos = blockIdx.x * 256 + tid;
    const int hh = pos >> 11, ww = pos & 2047;

    for (int n = 0; n < 8; n++) {
        const float* base = g_QKV + (size_t)(6 * n) * POSN + pos;
        float q0 = base[0];
        float q1 = base[POSN];

        float kin[2][9];
#pragma unroll
        for (int d = 0; d < 9; d++) {
            int dh = d / 3 - 1, dw = d % 3 - 1;
            bool ok = ((unsigned)(hh + dh) < 32u) && ((unsigned)(ww + dw) < 2048u);
            int off = dh * 2048 + dw;
            kin[0][d] = ok ? base[2 * POSN + off] : 0.f;
            kin[1][d] = ok ? base[3 * POSN + off] : 0.f;
        }
        float lg[9];
#pragma unroll
        for (int s = 0; s < 9; s++) {
            float k0 = kin[0][s], k1 = kin[1][s];
#pragma unroll
            for (int d = 0; d < 9; d++) {
                k0 += s_w[s * 9 + d]       * kin[0][d];
                k1 += s_w[(9 + s) * 9 + d] * kin[1][d];
            }
            k0 += s_b0[s]     + s_b1[s];
            k1 += s_b0[9 + s] + s_b1[9 + s];
            float r = s_r[n * 9 + s];
            lg[s] = SCALE * (q0 * k0 + q1 * k1 + (q0 + q1) * r);
        }
        float mx = lg[0];
#pragma unroll
        for (int s = 1; s < 9; s++) mx = fmaxf(mx, lg[s]);
        float att[9], sum = 0.f;
#pragma unroll
        for (int s = 0; s < 9; s++) { att[s] = __expf(lg[s] - mx); sum += att[s]; }
        float inv = 1.f / sum;

        float vin[2][9];
#pragma unroll
        for (int d = 0; d < 9; d++) {
            int dh = d / 3 - 1, dw = d % 3 - 1;
            bool ok = ((unsigned)(hh + dh) < 32u) && ((unsigned)(ww + dw) < 2048u);
            int off = dh * 2048 + dw;
            vin[0][d] = ok ? base[4 * POSN + off] : 0.f;
            vin[1][d] = ok ? base[5 * POSN + off] : 0.f;
        }
        float o0 = 0.f, o1 = 0.f;
#pragma unroll
        for (int s = 0; s < 9; s++) {
            float v0 = vin[0][s], v1 = vin[1][s];
#pragma unroll
            for (int d = 0; d < 9; d++) {
                v0 += s_w[s * 9 + d]       * vin[0][d];
                v1 += s_w[(9 + s) * 9 + d] * vin[1][d];
            }
            v0 += s_b0[s]     + s_b1[s];
            v1 += s_b0[9 + s] + s_b1[9 + s];
            o0 += att[s] * v0;
            o1 += att[s] * v1;
        }
        g_OB[(2 * n)     * POSN + pos] = o0 * inv;
        g_OB[(2 * n + 1) * POSN + pos] = o1 * inv;
    }
}

// ---------------------------------------------------------------------------
// K2c: proj 16->64 pointwise; output flat buffer doubles as [t][c] for fc2
// ---------------------------------------------------------------------------
__global__ __launch_bounds__(256) void k_proj(
    const float* __restrict__ proj_w, const float* __restrict__ proj_b)
{
    __shared__ float wp[16 * 64];  // wp[m][c]
    __shared__ float pb[64];
    const int tid = threadIdx.x;
    for (int i = tid; i < 1024; i += 256) {
        int c = i / 16, m = i % 16;
        wp[m * 64 + c] = proj_w[i];
    }
    if (tid < 64) pb[tid] = proj_b[tid];
    __syncthreads();

    const int pos = blockIdx.x * 256 + tid;
    float acc[64];
#pragma unroll
    for (int c = 0; c < 64; c++) acc[c] = pb[c];
    for (int m = 0; m < 16; m++) {
        float ov = g_OB[m * POSN + pos];
        const float4* wr = (const float4*)(wp + m * 64);
#pragma unroll
        for (int c4 = 0; c4 < 16; c4++) {
            float4 wv = wr[c4];
            acc[c4 * 4 + 0] += ov * wv.x;
            acc[c4 * 4 + 1] += ov * wv.y;
            acc[c4 * 4 + 2] += ov * wv.z;
            acc[c4 * 4 + 3] += ov * wv.w;
        }
    }
#pragma unroll
    for (int c = 0; c < 64; c++) g_P[c * POSN + pos] = acc[c];
}

// ---------------------------------------------------------------------------
// K3: fc2 (64->768) + bias + residual. 64 tokens/block, 256 threads.
// smem (floats): Pt@0 (64*65=4160), ws@4160 (128*64=8192), ot@12352 (64*129=8256)
// ---------------------------------------------------------------------------
__global__ __launch_bounds__(256) void k_fc2(
    const float* __restrict__ x, const float* __restrict__ fc2_w,
    const float* __restrict__ fc2_b, float* __restrict__ y)
{
    extern __shared__ float sm[];
    float* Pt = sm;
    float* ws = sm + 4160;
    float* ot = sm + 12352;

    const int tid = threadIdx.x;
    const int t0  = blockIdx.x * 64;
    const int lane = tid & 31, warp = tid >> 5;
    const int jb = warp * 16;

    for (int i = tid; i < 4096; i += 256) {
        int tt = i >> 6, c = i & 63;
        Pt[tt * 65 + c] = g_P[(size_t)(t0 + tt) * 64 + c];
    }

    for (int ccb = 0; ccb < 768; ccb += 128) {
        __syncthreads();
        for (int i = tid; i < 8192; i += 256) ws[i] = fc2_w[ccb * 64 + i];
        __syncthreads();

        float a0[16], a1[16];
#pragma unroll
        for (int j = 0; j < 16; j++) { a0[j] = 0.f; a1[j] = 0.f; }
        for (int k = 0; k < 64; k++) {
            float p0 = Pt[lane * 65 + k];
            float p1 = Pt[(lane + 32) * 65 + k];
#pragma unroll
            for (int j = 0; j < 16; j++) {
                float wv = ws[(jb + j) * 64 + k];   // warp-uniform -> broadcast
                a0[j] += p0 * wv;
                a1[j] += p1 * wv;
            }
        }
#pragma unroll
        for (int j = 0; j < 16; j++) {
            ot[lane * 129 + jb + j]        = a0[j];
            ot[(lane + 32) * 129 + jb + j] = a1[j];
        }
        __syncthreads();
        for (int i = tid; i < 8192; i += 256) {
            int tt = i >> 7, j = i & 127;
            size_t gi = (size_t)(t0 + tt) * 768 + ccb + j;
            y[gi] = x[gi] + fc2_b[ccb + j] + ot[tt * 129 + j];
        }
    }
}

// ---------------------------------------------------------------------------
extern "C" void kernel_launch(void* const* d_in, const int* in_sizes, int n_in,
                              void* d_out, int out_size)
{
    const float* x      = (const float*)d_in[0];
    const float* fc1_w  = (const float*)d_in[1];
    const float* fc1_b  = (const float*)d_in[2];
    const float* conv_w = (const float*)d_in[3];
    const float* conv_b = (const float*)d_in[4];
    const float* qkv_w  = (const float*)d_in[5];
    const float* qkv_b  = (const float*)d_in[6];
    const float* dep1_w = (const float*)d_in[7];
    const float* dep_b  = (const float*)d_in[8];
    const float* dep1_b = (const float*)d_in[9];
    const float* rpb    = (const float*)d_in[10];
    const float* proj_w = (const float*)d_in[11];
    const float* proj_b = (const float*)d_in[12];
    const float* fc2_w  = (const float*)d_in[13];
    const float* fc2_b  = (const float*)d_in[14];
    float* y = (float*)d_out;

    cudaFuncSetAttribute(k_fc1_conv, cudaFuncAttributeMaxDynamicSharedMemorySize, 83200);
    cudaFuncSetAttribute(k_fc2,      cudaFuncAttributeMaxDynamicSharedMemorySize, 82432);

    k_fc1_conv<<<512, 128, 83200>>>(x, fc1_w, fc1_b, conv_w, conv_b);
    k_qkv <<<256, 256>>>(qkv_w, qkv_b);
    k_attn<<<256, 256>>>(dep1_w, dep_b, dep1_b, rpb);
    k_proj<<<256, 256>>>(proj_w, proj_b);
    k_fc2 <<<1024, 256, 82432>>>(x, fc2_w, fc2_b, y);
}

// round 8
// speedup vs baseline: 2.3650x; 2.3650x over previous
#include <cuda_runtime.h>
#include <cuda_bf16.h>
#include <mma.h>
#include <math.h>
#include <stdint.h>

using namespace nvcuda;

#define POSN  65536
#define SCALE 0.35355339059327373f

// Scratch (device globals; allocation-free rule)
__device__ float g_G  [4194304];            // gelu out, flat: [t*64+c] == CHW [c][pos]
__device__ float g_QKV[48 * 65536];         // [j][pos]
__device__ float g_OB [16 * 65536];         // [m][pos]
__device__ __nv_bfloat16 g_Pb[4194304];     // proj out bf16, flat dual-view

// pack (lo=a, hi=b) into bf16x2
__device__ __forceinline__ uint32_t pk(float a, float b) {
    uint32_t r;
    asm("cvt.rn.bf16x2.f32 %0, %2, %1;" : "=r"(r) : "f"(a), "f"(b));
    return r;
}
__device__ __forceinline__ uint4 pk8(const float* s) {
    float4 a = *(const float4*)s, b = *(const float4*)(s + 4);
    uint4 w;
    w.x = pk(a.x, a.y); w.y = pk(a.z, a.w);
    w.z = pk(b.x, b.y); w.w = pk(b.z, b.w);
    return w;
}
__device__ __forceinline__ float gelu_exact(float h) {
    return 0.5f * h * (1.0f + erff(h * 0.70710678118654752f));
}

typedef wmma::fragment<wmma::matrix_a, 16, 16, 16, __nv_bfloat16, wmma::row_major> FragA;
typedef wmma::fragment<wmma::matrix_b, 16, 16, 16, __nv_bfloat16, wmma::col_major> FragB;
typedef wmma::fragment<wmma::accumulator, 16, 16, 16, float> FragC;

// SMEM strides (elements)
#define LDA 80   // bf16 A buffers: 160B row, 16B-aligned per 8-elem group
#define LDC 72   // fp32 C buffer:  288B row

// ---------------------------------------------------------------------------
// K1: fc1 (768->64, bf16 wmma) + 8x conv64 (bf16 wmma, SMEM ping-pong)
//     + L5->L7 skip + GELU.  128 tokens/CTA, 4 warps, 512 CTAs.
// SMEM bytes:
//   Cf   fp32 [128][72]  36864 @ 0
//   A0   bf16 [128][80]  20480 @ 36864
//   A1   bf16 [128][80]  20480 @ 57344
//   Bb   bf16 [64][64]    8192 @ 77824
//   biasF[64]+biasC[512]  2304 @ 86016     total 88320
// ---------------------------------------------------------------------------
__global__ __launch_bounds__(128) void k1_mma(
    const float* __restrict__ x, const float* __restrict__ fc1_w,
    const float* __restrict__ fc1_b, const float* __restrict__ conv_w,
    const float* __restrict__ conv_b)
{
    extern __shared__ char sm[];
    float*         Cf = (float*)sm;
    __nv_bfloat16* A0 = (__nv_bfloat16*)(sm + 36864);
    __nv_bfloat16* A1 = (__nv_bfloat16*)(sm + 57344);
    __nv_bfloat16* Bb = (__nv_bfloat16*)(sm + 77824);
    float* biasF = (float*)(sm + 86016);
    float* biasC = biasF + 64;

    const int tid = threadIdx.x;
    const int wid = tid >> 5;
    const int t0  = blockIdx.x * 128;
    const int m0  = wid * 32;

    if (tid < 64) biasF[tid] = fc1_b[tid];
    for (int i = tid; i < 512; i += 128) biasC[i] = conv_b[i];

    FragC acc[2][4];
#pragma unroll
    for (int mf = 0; mf < 2; mf++)
#pragma unroll
        for (int nf = 0; nf < 4; nf++) wmma::fill_fragment(acc[mf][nf], 0.0f);

    // ---- fc1: 12 K-chunks of 64 ----
    const float* xrow = x + (size_t)(t0 + tid) * 768;
    for (int kb = 0; kb < 12; kb++) {
        __syncthreads();
        // stage A chunk: thread = token row -> A0[tid][0..63] bf16
        {
            const float* s = xrow + kb * 64;
            uint4* d = (uint4*)(A0 + tid * LDA);
#pragma unroll
            for (int g = 0; g < 8; g++) d[g] = pk8(s + g * 8);
        }
        // stage B chunk [n=64][k=64] bf16 (row n, k contiguous)
        for (int cc = tid; cc < 512; cc += 128) {
            int n = cc >> 3, k0 = (cc & 7) * 8;
            ((uint4*)Bb)[cc] = pk8(fc1_w + (size_t)n * 768 + kb * 64 + k0);
        }
        __syncthreads();
#pragma unroll
        for (int ks = 0; ks < 4; ks++) {
            FragA a0f, a1f;
            wmma::load_matrix_sync(a0f, A0 + (m0)      * LDA + ks * 16, LDA);
            wmma::load_matrix_sync(a1f, A0 + (m0 + 16) * LDA + ks * 16, LDA);
#pragma unroll
            for (int nf = 0; nf < 4; nf++) {
                FragB bf;
                wmma::load_matrix_sync(bf, Bb + nf * 16 * 64 + ks * 16, 64);
                wmma::mma_sync(acc[0][nf], a0f, bf, acc[0][nf]);
                wmma::mma_sync(acc[1][nf], a1f, bf, acc[1][nf]);
            }
        }
    }
    // epilogue fc1 -> Cf -> (+biasF, bf16) -> A0
#pragma unroll
    for (int mf = 0; mf < 2; mf++)
#pragma unroll
        for (int nf = 0; nf < 4; nf++)
            wmma::store_matrix_sync(Cf + (m0 + mf * 16) * LDC + nf * 16,
                                    acc[mf][nf], LDC, wmma::mem_row_major);
    __syncthreads();
    {
        uint4* d = (uint4*)(A0 + tid * LDA);
#pragma unroll
        for (int g = 0; g < 8; g++) {
            float v[8];
#pragma unroll
            for (int i = 0; i < 8; i++)
                v[i] = Cf[tid * LDC + g * 8 + i] + biasF[g * 8 + i];
            uint4 w;
            w.x = pk(v[0], v[1]); w.y = pk(v[2], v[3]);
            w.z = pk(v[4], v[5]); w.w = pk(v[6], v[7]);
            d[g] = w;
        }
    }

    // ---- conv chain: cur ping-pongs A0->A1->A0...; L7 adds A0 (post-L5) ----
    __nv_bfloat16* cur = A0;
    for (int L = 0; L < 8; L++) {
        __syncthreads();
        // stage B = conv_w[L] [n][k] bf16
        for (int cc = tid; cc < 512; cc += 128) {
            int n = cc >> 3, k0 = (cc & 7) * 8;
            ((uint4*)Bb)[cc] = pk8(conv_w + L * 4096 + n * 64 + k0);
        }
        __syncthreads();
#pragma unroll
        for (int mf = 0; mf < 2; mf++)
#pragma unroll
            for (int nf = 0; nf < 4; nf++) wmma::fill_fragment(acc[mf][nf], 0.0f);
#pragma unroll
        for (int ks = 0; ks < 4; ks++) {
            FragA a0f, a1f;
            wmma::load_matrix_sync(a0f, cur + (m0)      * LDA + ks * 16, LDA);
            wmma::load_matrix_sync(a1f, cur + (m0 + 16) * LDA + ks * 16, LDA);
#pragma unroll
            for (int nf = 0; nf < 4; nf++) {
                FragB bf;
                wmma::load_matrix_sync(bf, Bb + nf * 16 * 64 + ks * 16, 64);
                wmma::mma_sync(acc[0][nf], a0f, bf, acc[0][nf]);
                wmma::mma_sync(acc[1][nf], a1f, bf, acc[1][nf]);
            }
        }
#pragma unroll
        for (int mf = 0; mf < 2; mf++)
#pragma unroll
            for (int nf = 0; nf < 4; nf++)
                wmma::store_matrix_sync(Cf + (m0 + mf * 16) * LDC + nf * 16,
                                        acc[mf][nf], LDC, wmma::mem_row_major);
        __syncthreads();

        if (L < 7) {
            __nv_bfloat16* out = (L & 1) ? A0 : A1;   // L0->A1, L1->A0, ...
            const float* bl = biasC + L * 64;
            uint4* d = (uint4*)(out + tid * LDA);
#pragma unroll
            for (int g = 0; g < 8; g++) {
                float v[8];
#pragma unroll
                for (int i = 0; i < 8; i++)
                    v[i] = Cf[tid * LDC + g * 8 + i] + bl[g * 8 + i];
                uint4 w;
                w.x = pk(v[0], v[1]); w.y = pk(v[2], v[3]);
                w.z = pk(v[4], v[5]); w.w = pk(v[6], v[7]);
                d[g] = w;
            }
            cur = out;
        } else {
            // final = C + b7 + h (h = A0 = post-L5 output, input of L6); GELU
            const float* bl = biasC + 7 * 64;
            float* gout = g_G + (size_t)(t0 + tid) * 64;
#pragma unroll
            for (int g = 0; g < 16; g++) {
                float4 v;
                int c = g * 4;
                v.x = gelu_exact(Cf[tid * LDC + c]     + bl[c]     + __bfloat162float(A0[tid * LDA + c]));
                v.y = gelu_exact(Cf[tid * LDC + c + 1] + bl[c + 1] + __bfloat162float(A0[tid * LDA + c + 1]));
                v.z = gelu_exact(Cf[tid * LDC + c + 2] + bl[c + 2] + __bfloat162float(A0[tid * LDA + c + 2]));
                v.w = gelu_exact(Cf[tid * LDC + c + 3] + bl[c + 3] + __bfloat162float(A0[tid * LDA + c + 3]));
                *(float4*)(gout + c) = v;
            }
        }
    }
}

// ---------------------------------------------------------------------------
// K2a: qkv pointwise 64->48 (fp32, L2-resident)
// ---------------------------------------------------------------------------
__global__ __launch_bounds__(256) void k_qkv(
    const float* __restrict__ qkv_w, const float* __restrict__ qkv_b)
{
    __shared__ float wq[64 * 48];
    __shared__ float bq[48];
    const int tid = threadIdx.x;
    for (int i = tid; i < 3072; i += 256) {
        int j = i / 64, c = i % 64;
        wq[c * 48 + j] = qkv_w[i];
    }
    if (tid < 48) bq[tid] = qkv_b[tid];
    __syncthreads();

    const int pos = blockIdx.x * 256 + tid;
    float acc[48];
#pragma unroll
    for (int j = 0; j < 48; j++) acc[j] = bq[j];
    for (int c = 0; c < 64; c++) {
        float xv = g_G[c * POSN + pos];
        const float4* wr = (const float4*)(wq + c * 48);
#pragma unroll
        for (int j4 = 0; j4 < 12; j4++) {
            float4 wv = wr[j4];
            acc[j4 * 4 + 0] += xv * wv.x;
            acc[j4 * 4 + 1] += xv * wv.y;
            acc[j4 * 4 + 2] += xv * wv.z;
            acc[j4 * 4 + 3] += xv * wv.w;
        }
    }
#pragma unroll
    for (int j = 0; j < 48; j++) g_QKV[j * POSN + pos] = acc[j];
}

// ---------------------------------------------------------------------------
// K2b: shift+dep1 convs on k/v, rpb, 9-way softmax, weighted v-sum (fp32)
// ---------------------------------------------------------------------------
__global__ __launch_bounds__(256) void k_attn(
    const float* __restrict__ dep1_w, const float* __restrict__ dep_b,
    const float* __restrict__ dep1_b, const float* __restrict__ rpb)
{
    __shared__ float s_w[162];
    __shared__ float s_b0[18];
    __shared__ float s_b1[18];
    __shared__ float s_r[72];
    const int tid = threadIdx.x;
    if (tid < 162) s_w[tid] = dep1_w[tid];
    if (tid < 18)  s_b0[tid] = dep_b[tid];
    if (tid < 18)  s_b1[tid] = dep1_b[tid];
    if (tid < 72)  s_r[tid] = rpb[tid];
    __syncthreads();

    const int pos = blockIdx.x * 256 + tid;
    const int hh = pos >> 11, ww = pos & 2047;

    for (int n = 0; n < 8; n++) {
        const float* base = g_QKV + (size_t)(6 * n) * POSN + pos;
        float q0 = base[0];
        float q1 = base[POSN];

        float kin[2][9];
#pragma unroll
        for (int d = 0; d < 9; d++) {
            int dh = d / 3 - 1, dw = d % 3 - 1;
            bool ok = ((unsigned)(hh + dh) < 32u) && ((unsigned)(ww + dw) < 2048u);
            int off = dh * 2048 + dw;
            kin[0][d] = ok ? base[2 * POSN + off] : 0.f;
            kin[1][d] = ok ? base[3 * POSN + off] : 0.f;
        }
        float lg[9];
#pragma unroll
        for (int s = 0; s < 9; s++) {
            float k0 = kin[0][s], k1 = kin[1][s];
#pragma unroll
            for (int d = 0; d < 9; d++) {
                k0 += s_w[s * 9 + d]       * kin[0][d];
                k1 += s_w[(9 + s) * 9 + d] * kin[1][d];
            }
            k0 += s_b0[s]     + s_b1[s];
            k1 += s_b0[9 + s] + s_b1[9 + s];
            float r = s_r[n * 9 + s];
            lg[s] = SCALE * (q0 * k0 + q1 * k1 + (q0 + q1) * r);
        }
        float mx = lg[0];
#pragma unroll
        for (int s = 1; s < 9; s++) mx = fmaxf(mx, lg[s]);
        float att[9], sum = 0.f;
#pragma unroll
        for (int s = 0; s < 9; s++) { att[s] = __expf(lg[s] - mx); sum += att[s]; }
        float inv = 1.f / sum;

        float vin[2][9];
#pragma unroll
        for (int d = 0; d < 9; d++) {
            int dh = d / 3 - 1, dw = d % 3 - 1;
            bool ok = ((unsigned)(hh + dh) < 32u) && ((unsigned)(ww + dw) < 2048u);
            int off = dh * 2048 + dw;
            vin[0][d] = ok ? base[4 * POSN + off] : 0.f;
            vin[1][d] = ok ? base[5 * POSN + off] : 0.f;
        }
        float o0 = 0.f, o1 = 0.f;
#pragma unroll
        for (int s = 0; s < 9; s++) {
            float v0 = vin[0][s], v1 = vin[1][s];
#pragma unroll
            for (int d = 0; d < 9; d++) {
                v0 += s_w[s * 9 + d]       * vin[0][d];
                v1 += s_w[(9 + s) * 9 + d] * vin[1][d];
            }
            v0 += s_b0[s]     + s_b1[s];
            v1 += s_b0[9 + s] + s_b1[9 + s];
            o0 += att[s] * v0;
            o1 += att[s] * v1;
        }
        g_OB[(2 * n)     * POSN + pos] = o0 * inv;
        g_OB[(2 * n + 1) * POSN + pos] = o1 * inv;
    }
}

// ---------------------------------------------------------------------------
// K2c: proj 16->64, emits bf16 A-operand for fc2 (dual-view flat buffer)
// ---------------------------------------------------------------------------
__global__ __launch_bounds__(256) void k_proj(
    const float* __restrict__ proj_w, const float* __restrict__ proj_b)
{
    __shared__ float wp[16 * 64];
    __shared__ float pb[64];
    const int tid = threadIdx.x;
    for (int i = tid; i < 1024; i += 256) {
        int c = i / 16, m = i % 16;
        wp[m * 64 + c] = proj_w[i];
    }
    if (tid < 64) pb[tid] = proj_b[tid];
    __syncthreads();

    const int pos = blockIdx.x * 256 + tid;
    float acc[64];
#pragma unroll
    for (int c = 0; c < 64; c++) acc[c] = pb[c];
    for (int m = 0; m < 16; m++) {
        float ov = g_OB[m * POSN + pos];
        const float4* wr = (const float4*)(wp + m * 64);
#pragma unroll
        for (int c4 = 0; c4 < 16; c4++) {
            float4 wv = wr[c4];
            acc[c4 * 4 + 0] += ov * wv.x;
            acc[c4 * 4 + 1] += ov * wv.y;
            acc[c4 * 4 + 2] += ov * wv.z;
            acc[c4 * 4 + 3] += ov * wv.w;
        }
    }
#pragma unroll
    for (int c = 0; c < 64; c++)
        g_Pb[(size_t)c * POSN + pos] = __float2bfloat16(acc[c]);
}

// ---------------------------------------------------------------------------
// K3: fc2 (64->768) bf16 wmma; A frags register-resident; bias+residual fused.
// 128 tokens/CTA, 4 warps, 512 CTAs.
// SMEM bytes: Abuf bf16[128][80] 20480 @0 ; Bb bf16[64][64] 8192 @20480 ;
//             Cf fp32[128][72] 36864 @28672 ; biasS 256 @65536  total 65792
// ---------------------------------------------------------------------------
__global__ __launch_bounds__(128) void k3_mma(
    const float* __restrict__ x, const float* __restrict__ fc2_w,
    const float* __restrict__ fc2_b, float* __restrict__ y)
{
    extern __shared__ char sm[];
    __nv_bfloat16* Abuf = (__nv_bfloat16*)sm;
    __nv_bfloat16* Bb   = (__nv_bfloat16*)(sm + 20480);
    float*         Cf   = (float*)(sm + 28672);
    float*         biasS= (float*)(sm + 65536);

    const int tid = threadIdx.x;
    const int wid = tid >> 5;
    const int t0  = blockIdx.x * 128;
    const int m0  = wid * 32;

    // stage A once: token row tid, 64 bf16 from g_Pb
    {
        const uint4* s = (const uint4*)(g_Pb + (size_t)(t0 + tid) * 64);
        uint4* d = (uint4*)(Abuf + tid * LDA);
#pragma unroll
        for (int g = 0; g < 8; g++) d[g] = s[g];
    }
    __syncthreads();

    FragA af[2][4];
#pragma unroll
    for (int mf = 0; mf < 2; mf++)
#pragma unroll
        for (int ks = 0; ks < 4; ks++)
            wmma::load_matrix_sync(af[mf][ks], Abuf + (m0 + mf * 16) * LDA + ks * 16, LDA);

    for (int nb = 0; nb < 12; nb++) {
        __syncthreads();
        for (int cc = tid; cc < 512; cc += 128) {
            int n = cc >> 3, k0 = (cc & 7) * 8;
            ((uint4*)Bb)[cc] = pk8(fc2_w + (size_t)(nb * 64 + n) * 64 + k0);
        }
        if (tid < 64) biasS[tid] = fc2_b[nb * 64 + tid];
        __syncthreads();

        FragC acc[2][4];
#pragma unroll
        for (int mf = 0; mf < 2; mf++)
#pragma unroll
            for (int nf = 0; nf < 4; nf++) wmma::fill_fragment(acc[mf][nf], 0.0f);
#pragma unroll
        for (int ks = 0; ks < 4; ks++)
#pragma unroll
            for (int nf = 0; nf < 4; nf++) {
                FragB bf;
                wmma::load_matrix_sync(bf, Bb + nf * 16 * 64 + ks * 16, 64);
                wmma::mma_sync(acc[0][nf], af[0][ks], bf, acc[0][nf]);
                wmma::mma_sync(acc[1][nf], af[1][ks], bf, acc[1][nf]);
            }
#pragma unroll
        for (int mf = 0; mf < 2; mf++)
#pragma unroll
            for (int nf = 0; nf < 4; nf++)
                wmma::store_matrix_sync(Cf + (m0 + mf * 16) * LDC + nf * 16,
                                        acc[mf][nf], LDC, wmma::mem_row_major);
        __syncthreads();

        // fused bias + residual, fully coalesced
        for (int f4 = tid; f4 < 2048; f4 += 128) {
            int tt = f4 >> 4, j = (f4 & 15) * 4;
            size_t gi = (size_t)(t0 + tt) * 768 + nb * 64 + j;
            float4 xv = *(const float4*)(x + gi);
            float4 cv = *(const float4*)(Cf + tt * LDC + j);
            float4 o;
            o.x = xv.x + cv.x + biasS[j];
            o.y = xv.y + cv.y + biasS[j + 1];
            o.z = xv.z + cv.z + biasS[j + 2];
            o.w = xv.w + cv.w + biasS[j + 3];
            *(float4*)(y + gi) = o;
        }
    }
}

// ---------------------------------------------------------------------------
extern "C" void kernel_launch(void* const* d_in, const int* in_sizes, int n_in,
                              void* d_out, int out_size)
{
    const float* x      = (const float*)d_in[0];
    const float* fc1_w  = (const float*)d_in[1];
    const float* fc1_b  = (const float*)d_in[2];
    const float* conv_w = (const float*)d_in[3];
    const float* conv_b = (const float*)d_in[4];
    const float* qkv_w  = (const float*)d_in[5];
    const float* qkv_b  = (const float*)d_in[6];
    const float* dep1_w = (const float*)d_in[7];
    const float* dep_b  = (const float*)d_in[8];
    const float* dep1_b = (const float*)d_in[9];
    const float* rpb    = (const float*)d_in[10];
    const float* proj_w = (const float*)d_in[11];
    const float* proj_b = (const float*)d_in[12];
    const float* fc2_w  = (const float*)d_in[13];
    const float* fc2_b  = (const float*)d_in[14];
    float* y = (float*)d_out;

    cudaFuncSetAttribute(k1_mma, cudaFuncAttributeMaxDynamicSharedMemorySize, 88320);
    cudaFuncSetAttribute(k3_mma, cudaFuncAttributeMaxDynamicSharedMemorySize, 65792);

    k1_mma<<<512, 128, 88320>>>(x, fc1_w, fc1_b, conv_w, conv_b);
    k_qkv <<<256, 256>>>(qkv_w, qkv_b);
    k_attn<<<256, 256>>>(dep1_w, dep_b, dep1_b, rpb);
    k_proj<<<256, 256>>>(proj_w, proj_b);
    k3_mma<<<512, 128, 65792>>>(x, fc2_w, fc2_b, y);
}

// round 10
// speedup vs baseline: 2.9162x; 1.2331x over previous
#include <cuda_runtime.h>
#include <cuda_bf16.h>
#include <mma.h>
#include <math.h>
#include <stdint.h>

using namespace nvcuda;

#define POSN  65536
#define SCALE 0.35355339059327373f

// Scratch (device globals; allocation-free rule)
__device__ float g_G  [4194304];            // gelu out, flat: [t*64+c] == CHW [c][pos]
__device__ float g_QKV[48 * 65536];         // [j][pos]
__device__ __nv_bfloat16 g_Pb[4194304];     // proj out bf16, flat dual-view

// pack (lo=a, hi=b) into bf16x2
__device__ __forceinline__ uint32_t pk(float a, float b) {
    uint32_t r;
    asm("cvt.rn.bf16x2.f32 %0, %2, %1;" : "=r"(r) : "f"(a), "f"(b));
    return r;
}
__device__ __forceinline__ uint2 pk4(float4 v) {
    uint2 r; r.x = pk(v.x, v.y); r.y = pk(v.z, v.w); return r;
}
__device__ __forceinline__ uint4 pk8(const float* s) {
    float4 a = *(const float4*)s, b = *(const float4*)(s + 4);
    uint4 w;
    w.x = pk(a.x, a.y); w.y = pk(a.z, a.w);
    w.z = pk(b.x, b.y); w.w = pk(b.z, b.w);
    return w;
}
__device__ __forceinline__ float gelu_exact(float h) {
    return 0.5f * h * (1.0f + erff(h * 0.70710678118654752f));
}

typedef wmma::fragment<wmma::matrix_a, 16, 16, 16, __nv_bfloat16, wmma::row_major> FragA;
typedef wmma::fragment<wmma::matrix_b, 16, 16, 16, __nv_bfloat16, wmma::col_major> FragB;
typedef wmma::fragment<wmma::accumulator, 16, 16, 16, float> FragC;

#define LDA 80   // bf16 A buffers: 160B rows
#define LDC 72   // fp32 C buffer

// ---------------------------------------------------------------------------
// K1: fc1 (768->64, bf16 wmma, reg-prefetch double-buffered) + 8x conv64
//     (bf16 wmma, SMEM ping-pong, weights prefetched) + L5->L7 skip + GELU.
// 128 tokens/CTA, 4 warps, 512 CTAs.
// SMEM: Cf f32[128][72] 36864 @0 ; A0 bf16 20480 @36864 ; A1 20480 @57344 ;
//       Bb0 8192 @77824 ; Bb1 8192 @86016 ; biasF 256 + biasC 2048 @94208
//       total 96512 -> 2 CTA/SM
// ---------------------------------------------------------------------------
__global__ __launch_bounds__(128) void k1_mma(
    const float* __restrict__ x, const float* __restrict__ fc1_w,
    const float* __restrict__ fc1_b, const float* __restrict__ conv_w,
    const float* __restrict__ conv_b)
{
    extern __shared__ char sm[];
    float*         Cf  = (float*)sm;
    __nv_bfloat16* A0  = (__nv_bfloat16*)(sm + 36864);
    __nv_bfloat16* A1  = (__nv_bfloat16*)(sm + 57344);
    __nv_bfloat16* Bb0 = (__nv_bfloat16*)(sm + 77824);
    __nv_bfloat16* Bb1 = (__nv_bfloat16*)(sm + 86016);
    float* biasF = (float*)(sm + 94208);
    float* biasC = biasF + 64;

    const int tid = threadIdx.x;
    const int wid = tid >> 5;
    const int t0  = blockIdx.x * 128;
    const int m0  = wid * 32;

    if (tid < 64) biasF[tid] = fc1_b[tid];
    for (int i = tid; i < 512; i += 128) biasC[i] = conv_b[i];

    // coalesced x-chunk mapping: idx = tid + 128*i -> row = idx>>4, c4 = idx&15
    const int xr_row = tid >> 4;          // base row (adds 8 per i)
    const int xr_c4  = tid & 15;          // fixed col-group
    const float* xbase = x + (size_t)t0 * 768;

    // B chunk mapping: cc = tid + 128*g -> n = cc>>3, k0 = (cc&7)*8
    uint2 xp[16];
    uint4 bp[4];

    // ---- prologue: stage chunk 0 ----
#pragma unroll
    for (int i = 0; i < 16; i++) {
        int row = xr_row + 8 * i;
        xp[i] = pk4(*(const float4*)(xbase + (size_t)row * 768 + xr_c4 * 4));
    }
#pragma unroll
    for (int g = 0; g < 4; g++) {
        int cc = tid + g * 128, n = cc >> 3, k0 = (cc & 7) * 8;
        bp[g] = pk8(fc1_w + (size_t)n * 768 + k0);
    }
#pragma unroll
    for (int i = 0; i < 16; i++)
        *(uint2*)(A0 + (xr_row + 8 * i) * LDA + xr_c4 * 4) = xp[i];
#pragma unroll
    for (int g = 0; g < 4; g++) ((uint4*)Bb0)[tid + g * 128] = bp[g];
    __syncthreads();

    FragC acc[2][4];
#pragma unroll
    for (int mf = 0; mf < 2; mf++)
#pragma unroll
        for (int nf = 0; nf < 4; nf++) wmma::fill_fragment(acc[mf][nf], 0.0f);

    // ---- fc1 mainloop: 12 K-chunks, double-buffered ----
    for (int kb = 0; kb < 12; kb++) {
        __nv_bfloat16* Acur = (kb & 1) ? A1 : A0;
        __nv_bfloat16* Bcur = (kb & 1) ? Bb1 : Bb0;
        __nv_bfloat16* Anxt = (kb & 1) ? A0 : A1;
        __nv_bfloat16* Bnxt = (kb & 1) ? Bb0 : Bb1;

        if (kb < 11) {
#pragma unroll
            for (int i = 0; i < 16; i++) {
                int row = xr_row + 8 * i;
                xp[i] = pk4(*(const float4*)(xbase + (size_t)row * 768 + (kb + 1) * 64 + xr_c4 * 4));
            }
#pragma unroll
            for (int g = 0; g < 4; g++) {
                int cc = tid + g * 128, n = cc >> 3, k0 = (cc & 7) * 8;
                bp[g] = pk8(fc1_w + (size_t)n * 768 + (kb + 1) * 64 + k0);
            }
        } else {
            // prefetch conv layer 0 weights into Bb0
#pragma unroll
            for (int g = 0; g < 4; g++) {
                int cc = tid + g * 128, n = cc >> 3, k0 = (cc & 7) * 8;
                bp[g] = pk8(conv_w + n * 64 + k0);
            }
        }

#pragma unroll
        for (int ks = 0; ks < 4; ks++) {
            FragA a0f, a1f;
            wmma::load_matrix_sync(a0f, Acur + (m0)      * LDA + ks * 16, LDA);
            wmma::load_matrix_sync(a1f, Acur + (m0 + 16) * LDA + ks * 16, LDA);
#pragma unroll
            for (int nf = 0; nf < 4; nf++) {
                FragB bf;
                wmma::load_matrix_sync(bf, Bcur + nf * 16 * 64 + ks * 16, 64);
                wmma::mma_sync(acc[0][nf], a0f, bf, acc[0][nf]);
                wmma::mma_sync(acc[1][nf], a1f, bf, acc[1][nf]);
            }
        }

        if (kb < 11) {
#pragma unroll
            for (int i = 0; i < 16; i++)
                *(uint2*)(Anxt + (xr_row + 8 * i) * LDA + xr_c4 * 4) = xp[i];
#pragma unroll
            for (int g = 0; g < 4; g++) ((uint4*)Bnxt)[tid + g * 128] = bp[g];
        } else {
#pragma unroll
            for (int g = 0; g < 4; g++) ((uint4*)Bb0)[tid + g * 128] = bp[g];
        }
        __syncthreads();
    }

    // epilogue fc1 -> Cf -> (+biasF, bf16) -> A0
#pragma unroll
    for (int mf = 0; mf < 2; mf++)
#pragma unroll
        for (int nf = 0; nf < 4; nf++)
            wmma::store_matrix_sync(Cf + (m0 + mf * 16) * LDC + nf * 16,
                                    acc[mf][nf], LDC, wmma::mem_row_major);
    __syncthreads();
    {
        uint2* d = (uint2*)(A0 + tid * LDA);
#pragma unroll
        for (int g = 0; g < 16; g++) {
            float4 v = *(const float4*)(Cf + tid * LDC + g * 4);
            v.x += biasF[g * 4];     v.y += biasF[g * 4 + 1];
            v.z += biasF[g * 4 + 2]; v.w += biasF[g * 4 + 3];
            d[g] = pk4(v);
        }
    }
    __syncthreads();

    // ---- conv chain: cur A0->A1->A0... ; weights prefetched into Bb ping-pong ----
    __nv_bfloat16* cur = A0;
    for (int L = 0; L < 8; L++) {
        __nv_bfloat16* Bcur = (L & 1) ? Bb1 : Bb0;
        __nv_bfloat16* Bnxt = (L & 1) ? Bb0 : Bb1;

        if (L < 7) {
#pragma unroll
            for (int g = 0; g < 4; g++) {
                int cc = tid + g * 128, n = cc >> 3, k0 = (cc & 7) * 8;
                bp[g] = pk8(conv_w + (L + 1) * 4096 + n * 64 + k0);
            }
        }

#pragma unroll
        for (int mf = 0; mf < 2; mf++)
#pragma unroll
            for (int nf = 0; nf < 4; nf++) wmma::fill_fragment(acc[mf][nf], 0.0f);
#pragma unroll
        for (int ks = 0; ks < 4; ks++) {
            FragA a0f, a1f;
            wmma::load_matrix_sync(a0f, cur + (m0)      * LDA + ks * 16, LDA);
            wmma::load_matrix_sync(a1f, cur + (m0 + 16) * LDA + ks * 16, LDA);
#pragma unroll
            for (int nf = 0; nf < 4; nf++) {
                FragB bf;
                wmma::load_matrix_sync(bf, Bcur + nf * 16 * 64 + ks * 16, 64);
                wmma::mma_sync(acc[0][nf], a0f, bf, acc[0][nf]);
                wmma::mma_sync(acc[1][nf], a1f, bf, acc[1][nf]);
            }
        }
#pragma unroll
        for (int mf = 0; mf < 2; mf++)
#pragma unroll
            for (int nf = 0; nf < 4; nf++)
                wmma::store_matrix_sync(Cf + (m0 + mf * 16) * LDC + nf * 16,
                                        acc[mf][nf], LDC, wmma::mem_row_major);
        if (L < 7) {
#pragma unroll
            for (int g = 0; g < 4; g++) ((uint4*)Bnxt)[tid + g * 128] = bp[g];
        }
        __syncthreads();

        if (L < 7) {
            __nv_bfloat16* out = (L & 1) ? A0 : A1;
            const float* bl = biasC + L * 64;
            uint2* d = (uint2*)(out + tid * LDA);
#pragma unroll
            for (int g = 0; g < 16; g++) {
                float4 v = *(const float4*)(Cf + tid * LDC + g * 4);
                v.x += bl[g * 4];     v.y += bl[g * 4 + 1];
                v.z += bl[g * 4 + 2]; v.w += bl[g * 4 + 3];
                d[g] = pk4(v);
            }
            cur = out;
        } else {
            // final = C + b7 + h (A0 = post-L5, input of L6); GELU; write g_G
            const float* bl = biasC + 7 * 64;
            float* gout = g_G + (size_t)(t0 + tid) * 64;
#pragma unroll
            for (int g = 0; g < 16; g++) {
                float4 v;
                int c = g * 4;
                v.x = gelu_exact(Cf[tid * LDC + c]     + bl[c]     + __bfloat162float(A0[tid * LDA + c]));
                v.y = gelu_exact(Cf[tid * LDC + c + 1] + bl[c + 1] + __bfloat162float(A0[tid * LDA + c + 1]));
                v.z = gelu_exact(Cf[tid * LDC + c + 2] + bl[c + 2] + __bfloat162float(A0[tid * LDA + c + 2]));
                v.w = gelu_exact(Cf[tid * LDC + c + 3] + bl[c + 3] + __bfloat162float(A0[tid * LDA + c + 3]));
                *(float4*)(gout + c) = v;
            }
        }
        __syncthreads();
    }
}

// ---------------------------------------------------------------------------
// K2a: qkv pointwise 64->48, float2-vectorized (2 positions / thread)
// ---------------------------------------------------------------------------
__global__ __launch_bounds__(128) void k_qkv(
    const float* __restrict__ qkv_w, const float* __restrict__ qkv_b)
{
    __shared__ float wq[64 * 48];   // wq[c][j]
    __shared__ float bq[48];
    const int tid = threadIdx.x;
    for (int i = tid; i < 3072; i += 128) {
        int j = i / 64, c = i % 64;
        wq[c * 48 + j] = qkv_w[i];
    }
    if (tid < 48) bq[tid] = qkv_b[tid];
    __syncthreads();

    const int pos = (blockIdx.x * 128 + tid) * 2;
    float2 acc[48];
#pragma unroll
    for (int j = 0; j < 48; j++) { acc[j].x = bq[j]; acc[j].y = bq[j]; }
    for (int c = 0; c < 64; c++) {
        float2 xv = *(const float2*)(g_G + (size_t)c * POSN + pos);
        const float4* wr = (const float4*)(wq + c * 48);
#pragma unroll
        for (int j4 = 0; j4 < 12; j4++) {
            float4 wv = wr[j4];
            acc[j4 * 4 + 0].x += xv.x * wv.x; acc[j4 * 4 + 0].y += xv.y * wv.x;
            acc[j4 * 4 + 1].x += xv.x * wv.y; acc[j4 * 4 + 1].y += xv.y * wv.y;
            acc[j4 * 4 + 2].x += xv.x * wv.z; acc[j4 * 4 + 2].y += xv.y * wv.z;
            acc[j4 * 4 + 3].x += xv.x * wv.w; acc[j4 * 4 + 3].y += xv.y * wv.w;
        }
    }
#pragma unroll
    for (int j = 0; j < 48; j++)
        *(float2*)(g_QKV + (size_t)j * POSN + pos) = acc[j];
}

// ---------------------------------------------------------------------------
// K2b: attention + proj, fused. Block = 256 w-positions in one h-row.
// k/v 3x258 halo tiles staged in SMEM per head; o[16] in regs; proj epilogue
// writes bf16 g_Pb directly (dual-view A operand for fc2).
// ---------------------------------------------------------------------------
#define T_R 260
#define T_CH 780    // 3*260
__global__ __launch_bounds__(256) void k_attn_proj(
    const float* __restrict__ dep1_w, const float* __restrict__ dep_b,
    const float* __restrict__ dep1_b, const float* __restrict__ rpb,
    const float* __restrict__ proj_w, const float* __restrict__ proj_b)
{
    __shared__ float tile[4 * T_CH];  // [ch][3][260]
    __shared__ float s_w[162];
    __shared__ float s_b0[18];
    __shared__ float s_b1[18];
    __shared__ float s_r[72];
    __shared__ float wp[16 * 64];     // wp[m][c]
    __shared__ float pb[64];

    const int tid = threadIdx.x;
    if (tid < 162) s_w[tid] = dep1_w[tid];
    if (tid < 18)  s_b0[tid] = dep_b[tid];
    if (tid < 18)  s_b1[tid] = dep1_b[tid];
    if (tid < 72)  s_r[tid] = rpb[tid];
    for (int i = tid; i < 1024; i += 256) {
        int c = i / 16, m = i % 16;
        wp[m * 64 + c] = proj_w[i];
    }
    if (tid < 64) pb[tid] = proj_b[tid];

    const int hh = blockIdx.x >> 3;
    const int w0 = (blockIdx.x & 7) * 256;
    const int pos = hh * 2048 + w0 + tid;
    const int tc = tid + 1;

    float o[16];

    for (int n = 0; n < 8; n++) {
        __syncthreads();
        // stage k0,k1,v0,v1 halo tiles: rows hh-1..hh+1, cols w0-1..w0+256
        for (int i = tid; i < 4 * 774; i += 256) {
            int ch = i / 774, rem = i % 774;
            int r = rem / 258, c = rem % 258;
            int hr = hh - 1 + r, wc = w0 - 1 + c;
            float v = 0.f;
            if ((unsigned)hr < 32u && (unsigned)wc < 2048u)
                v = g_QKV[(size_t)(6 * n + 2 + ch) * POSN + hr * 2048 + wc];
            tile[ch * T_CH + r * T_R + c] = v;
        }
        __syncthreads();

        float q0 = g_QKV[(size_t)(6 * n)     * POSN + pos];
        float q1 = g_QKV[(size_t)(6 * n + 1) * POSN + pos];

        float kin[2][9];
#pragma unroll
        for (int d = 0; d < 9; d++) {
            int r = d / 3, dw = d % 3 - 1;
            kin[0][d] = tile[0 * T_CH + r * T_R + tc + dw];
            kin[1][d] = tile[1 * T_CH + r * T_R + tc + dw];
        }
        float lg[9];
#pragma unroll
        for (int s = 0; s < 9; s++) {
            float k0 = kin[0][s], k1 = kin[1][s];
#pragma unroll
            for (int d = 0; d < 9; d++) {
                k0 += s_w[s * 9 + d]       * kin[0][d];
                k1 += s_w[(9 + s) * 9 + d] * kin[1][d];
            }
            k0 += s_b0[s]     + s_b1[s];
            k1 += s_b0[9 + s] + s_b1[9 + s];
            float r = s_r[n * 9 + s];
            lg[s] = SCALE * (q0 * k0 + q1 * k1 + (q0 + q1) * r);
        }
        float mx = lg[0];
#pragma unroll
        for (int s = 1; s < 9; s++) mx = fmaxf(mx, lg[s]);
        float att[9], sum = 0.f;
#pragma unroll
        for (int s = 0; s < 9; s++) { att[s] = __expf(lg[s] - mx); sum += att[s]; }
        float inv = 1.f / sum;

        float vin[2][9];
#pragma unroll
        for (int d = 0; d < 9; d++) {
            int r = d / 3, dw = d % 3 - 1;
            vin[0][d] = tile[2 * T_CH + r * T_R + tc + dw];
            vin[1][d] = tile[3 * T_CH + r * T_R + tc + dw];
        }
        float o0 = 0.f, o1 = 0.f;
#pragma unroll
        for (int s = 0; s < 9; s++) {
            float v0 = vin[0][s], v1 = vin[1][s];
#pragma unroll
            for (int d = 0; d < 9; d++) {
                v0 += s_w[s * 9 + d]       * vin[0][d];
                v1 += s_w[(9 + s) * 9 + d] * vin[1][d];
            }
            v0 += s_b0[s]     + s_b1[s];
            v1 += s_b0[9 + s] + s_b1[9 + s];
            o0 += att[s] * v0;
            o1 += att[s] * v1;
        }
        o[2 * n]     = o0 * inv;
        o[2 * n + 1] = o1 * inv;
    }

    // fused proj: out[c] = pb[c] + sum_m o[m]*wp[m][c]  -> bf16 g_Pb (CHW view)
#pragma unroll 4
    for (int c = 0; c < 64; c++) {
        float s = pb[c];
#pragma unroll
        for (int m = 0; m < 16; m++) s += o[m] * wp[m * 64 + c];
        g_Pb[(size_t)c * POSN + pos] = __float2bfloat16(s);
    }
}

// ---------------------------------------------------------------------------
// K3: fc2 (64->768) bf16 wmma; A frags register-resident; B double-buffered
// with register prefetch; bias+residual fused, coalesced.
// SMEM: Abuf 20480 @0 ; Bb0 8192 @20480 ; Bb1 8192 @28672 ; Cf 36864 @36864
//       total 73728 -> 3 CTA/SM
// ---------------------------------------------------------------------------
__global__ __launch_bounds__(128) void k3_mma(
    const float* __restrict__ x, const float* __restrict__ fc2_w,
    const float* __restrict__ fc2_b, float* __restrict__ y)
{
    extern __shared__ char sm[];
    __nv_bfloat16* Abuf = (__nv_bfloat16*)sm;
    __nv_bfloat16* Bb0  = (__nv_bfloat16*)(sm + 20480);
    __nv_bfloat16* Bb1  = (__nv_bfloat16*)(sm + 28672);
    float*         Cf   = (float*)(sm + 36864);

    const int tid = threadIdx.x;
    const int wid = tid >> 5;
    const int t0  = blockIdx.x * 128;
    const int m0  = wid * 32;

    uint4 bp[4];

    // stage A (bf16 from g_Pb) + first B chunk
    {
        const uint4* s = (const uint4*)(g_Pb + (size_t)(t0 + tid) * 64);
        uint4* d = (uint4*)(Abuf + tid * LDA);
#pragma unroll
        for (int g = 0; g < 8; g++) d[g] = s[g];
    }
#pragma unroll
    for (int g = 0; g < 4; g++) {
        int cc = tid + g * 128, n = cc >> 3, k0 = (cc & 7) * 8;
        bp[g] = pk8(fc2_w + (size_t)n * 64 + k0);
    }
#pragma unroll
    for (int g = 0; g < 4; g++) ((uint4*)Bb0)[tid + g * 128] = bp[g];
    __syncthreads();

    FragA af[2][4];
#pragma unroll
    for (int mf = 0; mf < 2; mf++)
#pragma unroll
        for (int ks = 0; ks < 4; ks++)
            wmma::load_matrix_sync(af[mf][ks], Abuf + (m0 + mf * 16) * LDA + ks * 16, LDA);

    for (int nb = 0; nb < 12; nb++) {
        __nv_bfloat16* Bcur = (nb & 1) ? Bb1 : Bb0;
        __nv_bfloat16* Bnxt = (nb & 1) ? Bb0 : Bb1;

        if (nb < 11) {
#pragma unroll
            for (int g = 0; g < 4; g++) {
                int cc = tid + g * 128, n = cc >> 3, k0 = (cc & 7) * 8;
                bp[g] = pk8(fc2_w + (size_t)((nb + 1) * 64 + n) * 64 + k0);
            }
        }

        FragC acc[2][4];
#pragma unroll
        for (int mf = 0; mf < 2; mf++)
#pragma unroll
            for (int nf = 0; nf < 4; nf++) wmma::fill_fragment(acc[mf][nf], 0.0f);
#pragma unroll
        for (int ks = 0; ks < 4; ks++)
#pragma unroll
            for (int nf = 0; nf < 4; nf++) {
                FragB bf;
                wmma::load_matrix_sync(bf, Bcur + nf * 16 * 64 + ks * 16, 64);
                wmma::mma_sync(acc[0][nf], af[0][ks], bf, acc[0][nf]);
                wmma::mma_sync(acc[1][nf], af[1][ks], bf, acc[1][nf]);
            }
#pragma unroll
        for (int mf = 0; mf < 2; mf++)
#pragma unroll
            for (int nf = 0; nf < 4; nf++)
                wmma::store_matrix_sync(Cf + (m0 + mf * 16) * LDC + nf * 16,
                                        acc[mf][nf], LDC, wmma::mem_row_major);
        if (nb < 11) {
#pragma unroll
            for (int g = 0; g < 4; g++) ((uint4*)Bnxt)[tid + g * 128] = bp[g];
        }
        __syncthreads();

        // fused bias + residual, coalesced
        for (int f4 = tid; f4 < 2048; f4 += 128) {
            int tt = f4 >> 4, j = (f4 & 15) * 4;
            size_t gi = (size_t)(t0 + tt) * 768 + nb * 64 + j;
            float4 xv = *(const float4*)(x + gi);
            float4 cv = *(const float4*)(Cf + tt * LDC + j);
            float4 bv = __ldg((const float4*)(fc2_b + nb * 64 + j));
            float4 o;
            o.x = xv.x + cv.x + bv.x;
            o.y = xv.y + cv.y + bv.y;
            o.z = xv.z + cv.z + bv.z;
            o.w = xv.w + cv.w + bv.w;
            *(float4*)(y + gi) = o;
        }
        __syncthreads();
    }
}

// ---------------------------------------------------------------------------
extern "C" void kernel_launch(void* const* d_in, const int* in_sizes, int n_in,
                              void* d_out, int out_size)
{
    const float* x      = (const float*)d_in[0];
    const float* fc1_w  = (const float*)d_in[1];
    const float* fc1_b  = (const float*)d_in[2];
    const float* conv_w = (const float*)d_in[3];
    const float* conv_b = (const float*)d_in[4];
    const float* qkv_w  = (const float*)d_in[5];
    const float* qkv_b  = (const float*)d_in[6];
    const float* dep1_w = (const float*)d_in[7];
    const float* dep_b  = (const float*)d_in[8];
    const float* dep1_b = (const float*)d_in[9];
    const float* rpb    = (const float*)d_in[10];
    const float* proj_w = (const float*)d_in[11];
    const float* proj_b = (const float*)d_in[12];
    const float* fc2_w  = (const float*)d_in[13];
    const float* fc2_b  = (const float*)d_in[14];
    float* y = (float*)d_out;

    cudaFuncSetAttribute(k1_mma, cudaFuncAttributeMaxDynamicSharedMemorySize, 96512);
    cudaFuncSetAttribute(k3_mma, cudaFuncAttributeMaxDynamicSharedMemorySize, 73728);

    k1_mma<<<512, 128, 96512>>>(x, fc1_w, fc1_b, conv_w, conv_b);
    k_qkv <<<256, 128>>>(qkv_w, qkv_b);
    k_attn_proj<<<256, 256>>>(dep1_w, dep_b, dep1_b, rpb, proj_w, proj_b);
    k3_mma<<<512, 128, 73728>>>(x, fc2_w, fc2_b, y);
}

// round 12
// speedup vs baseline: 3.0071x; 1.0312x over previous
#include <cuda_runtime.h>
#include <cuda_bf16.h>
#include <mma.h>
#include <math.h>
#include <stdint.h>

using namespace nvcuda;

#define POSN  65536
#define SCALE 0.35355339059327373f

// Scratch (device globals; allocation-free rule)
__device__ float g_G  [4194304];            // gelu out, flat: [t*64+c] == CHW [c][pos]
__device__ float g_QKV[48 * 65536];         // [j][pos]
__device__ __nv_bfloat16 g_Pb[4194304];     // proj out bf16, flat dual-view

// pack (lo=a, hi=b) into bf16x2
__device__ __forceinline__ uint32_t pk(float a, float b) {
    uint32_t r;
    asm("cvt.rn.bf16x2.f32 %0, %2, %1;" : "=r"(r) : "f"(a), "f"(b));
    return r;
}
__device__ __forceinline__ uint2 pk4(float4 v) {
    uint2 r; r.x = pk(v.x, v.y); r.y = pk(v.z, v.w); return r;
}
__device__ __forceinline__ uint4 pk8(const float* s) {
    float4 a = *(const float4*)s, b = *(const float4*)(s + 4);
    uint4 w;
    w.x = pk(a.x, a.y); w.y = pk(a.z, a.w);
    w.z = pk(b.x, b.y); w.w = pk(b.z, b.w);
    return w;
}
__device__ __forceinline__ float gelu_exact(float h) {
    return 0.5f * h * (1.0f + erff(h * 0.70710678118654752f));
}

typedef wmma::fragment<wmma::matrix_a, 16, 16, 16, __nv_bfloat16, wmma::row_major> FragA;
typedef wmma::fragment<wmma::matrix_b, 16, 16, 16, __nv_bfloat16, wmma::col_major> FragB;
typedef wmma::fragment<wmma::accumulator, 16, 16, 16, float> FragC;

#define LDA 80   // bf16 A buffers: 160B rows
#define LDC 72   // fp32 C buffer

// ---------------------------------------------------------------------------
// K1: fc1 (768->64, bf16 wmma, reg-prefetch double-buffered) + 8x conv64
//     (bf16 wmma, SMEM ping-pong, weights prefetched) + L5->L7 skip + GELU.
// 128 tokens/CTA, 4 warps, 512 CTAs.  (unchanged from round 10)
// ---------------------------------------------------------------------------
__global__ __launch_bounds__(128) void k1_mma(
    const float* __restrict__ x, const float* __restrict__ fc1_w,
    const float* __restrict__ fc1_b, const float* __restrict__ conv_w,
    const float* __restrict__ conv_b)
{
    extern __shared__ char sm[];
    float*         Cf  = (float*)sm;
    __nv_bfloat16* A0  = (__nv_bfloat16*)(sm + 36864);
    __nv_bfloat16* A1  = (__nv_bfloat16*)(sm + 57344);
    __nv_bfloat16* Bb0 = (__nv_bfloat16*)(sm + 77824);
    __nv_bfloat16* Bb1 = (__nv_bfloat16*)(sm + 86016);
    float* biasF = (float*)(sm + 94208);
    float* biasC = biasF + 64;

    const int tid = threadIdx.x;
    const int wid = tid >> 5;
    const int t0  = blockIdx.x * 128;
    const int m0  = wid * 32;

    if (tid < 64) biasF[tid] = fc1_b[tid];
    for (int i = tid; i < 512; i += 128) biasC[i] = conv_b[i];

    const int xr_row = tid >> 4;
    const int xr_c4  = tid & 15;
    const float* xbase = x + (size_t)t0 * 768;

    uint2 xp[16];
    uint4 bp[4];

    // prologue: stage chunk 0
#pragma unroll
    for (int i = 0; i < 16; i++) {
        int row = xr_row + 8 * i;
        xp[i] = pk4(*(const float4*)(xbase + (size_t)row * 768 + xr_c4 * 4));
    }
#pragma unroll
    for (int g = 0; g < 4; g++) {
        int cc = tid + g * 128, n = cc >> 3, k0 = (cc & 7) * 8;
        bp[g] = pk8(fc1_w + (size_t)n * 768 + k0);
    }
#pragma unroll
    for (int i = 0; i < 16; i++)
        *(uint2*)(A0 + (xr_row + 8 * i) * LDA + xr_c4 * 4) = xp[i];
#pragma unroll
    for (int g = 0; g < 4; g++) ((uint4*)Bb0)[tid + g * 128] = bp[g];
    __syncthreads();

    FragC acc[2][4];
#pragma unroll
    for (int mf = 0; mf < 2; mf++)
#pragma unroll
        for (int nf = 0; nf < 4; nf++) wmma::fill_fragment(acc[mf][nf], 0.0f);

    for (int kb = 0; kb < 12; kb++) {
        __nv_bfloat16* Acur = (kb & 1) ? A1 : A0;
        __nv_bfloat16* Bcur = (kb & 1) ? Bb1 : Bb0;
        __nv_bfloat16* Anxt = (kb & 1) ? A0 : A1;
        __nv_bfloat16* Bnxt = (kb & 1) ? Bb0 : Bb1;

        if (kb < 11) {
#pragma unroll
            for (int i = 0; i < 16; i++) {
                int row = xr_row + 8 * i;
                xp[i] = pk4(*(const float4*)(xbase + (size_t)row * 768 + (kb + 1) * 64 + xr_c4 * 4));
            }
#pragma unroll
            for (int g = 0; g < 4; g++) {
                int cc = tid + g * 128, n = cc >> 3, k0 = (cc & 7) * 8;
                bp[g] = pk8(fc1_w + (size_t)n * 768 + (kb + 1) * 64 + k0);
            }
        } else {
#pragma unroll
            for (int g = 0; g < 4; g++) {
                int cc = tid + g * 128, n = cc >> 3, k0 = (cc & 7) * 8;
                bp[g] = pk8(conv_w + n * 64 + k0);
            }
        }

#pragma unroll
        for (int ks = 0; ks < 4; ks++) {
            FragA a0f, a1f;
            wmma::load_matrix_sync(a0f, Acur + (m0)      * LDA + ks * 16, LDA);
            wmma::load_matrix_sync(a1f, Acur + (m0 + 16) * LDA + ks * 16, LDA);
#pragma unroll
            for (int nf = 0; nf < 4; nf++) {
                FragB bf;
                wmma::load_matrix_sync(bf, Bcur + nf * 16 * 64 + ks * 16, 64);
                wmma::mma_sync(acc[0][nf], a0f, bf, acc[0][nf]);
                wmma::mma_sync(acc[1][nf], a1f, bf, acc[1][nf]);
            }
        }

        if (kb < 11) {
#pragma unroll
            for (int i = 0; i < 16; i++)
                *(uint2*)(Anxt + (xr_row + 8 * i) * LDA + xr_c4 * 4) = xp[i];
#pragma unroll
            for (int g = 0; g < 4; g++) ((uint4*)Bnxt)[tid + g * 128] = bp[g];
        } else {
#pragma unroll
            for (int g = 0; g < 4; g++) ((uint4*)Bb0)[tid + g * 128] = bp[g];
        }
        __syncthreads();
    }

    // epilogue fc1 -> Cf -> (+biasF, bf16) -> A0
#pragma unroll
    for (int mf = 0; mf < 2; mf++)
#pragma unroll
        for (int nf = 0; nf < 4; nf++)
            wmma::store_matrix_sync(Cf + (m0 + mf * 16) * LDC + nf * 16,
                                    acc[mf][nf], LDC, wmma::mem_row_major);
    __syncthreads();
    {
        uint2* d = (uint2*)(A0 + tid * LDA);
#pragma unroll
        for (int g = 0; g < 16; g++) {
            float4 v = *(const float4*)(Cf + tid * LDC + g * 4);
            v.x += biasF[g * 4];     v.y += biasF[g * 4 + 1];
            v.z += biasF[g * 4 + 2]; v.w += biasF[g * 4 + 3];
            d[g] = pk4(v);
        }
    }
    __syncthreads();

    // conv chain
    __nv_bfloat16* cur = A0;
    for (int L = 0; L < 8; L++) {
        __nv_bfloat16* Bcur = (L & 1) ? Bb1 : Bb0;
        __nv_bfloat16* Bnxt = (L & 1) ? Bb0 : Bb1;

        if (L < 7) {
#pragma unroll
            for (int g = 0; g < 4; g++) {
                int cc = tid + g * 128, n = cc >> 3, k0 = (cc & 7) * 8;
                bp[g] = pk8(conv_w + (L + 1) * 4096 + n * 64 + k0);
            }
        }

#pragma unroll
        for (int mf = 0; mf < 2; mf++)
#pragma unroll
            for (int nf = 0; nf < 4; nf++) wmma::fill_fragment(acc[mf][nf], 0.0f);
#pragma unroll
        for (int ks = 0; ks < 4; ks++) {
            FragA a0f, a1f;
            wmma::load_matrix_sync(a0f, cur + (m0)      * LDA + ks * 16, LDA);
            wmma::load_matrix_sync(a1f, cur + (m0 + 16) * LDA + ks * 16, LDA);
#pragma unroll
            for (int nf = 0; nf < 4; nf++) {
                FragB bf;
                wmma::load_matrix_sync(bf, Bcur + nf * 16 * 64 + ks * 16, 64);
                wmma::mma_sync(acc[0][nf], a0f, bf, acc[0][nf]);
                wmma::mma_sync(acc[1][nf], a1f, bf, acc[1][nf]);
            }
        }
#pragma unroll
        for (int mf = 0; mf < 2; mf++)
#pragma unroll
            for (int nf = 0; nf < 4; nf++)
                wmma::store_matrix_sync(Cf + (m0 + mf * 16) * LDC + nf * 16,
                                        acc[mf][nf], LDC, wmma::mem_row_major);
        if (L < 7) {
#pragma unroll
            for (int g = 0; g < 4; g++) ((uint4*)Bnxt)[tid + g * 128] = bp[g];
        }
        __syncthreads();

        if (L < 7) {
            __nv_bfloat16* out = (L & 1) ? A0 : A1;
            const float* bl = biasC + L * 64;
            uint2* d = (uint2*)(out + tid * LDA);
#pragma unroll
            for (int g = 0; g < 16; g++) {
                float4 v = *(const float4*)(Cf + tid * LDC + g * 4);
                v.x += bl[g * 4];     v.y += bl[g * 4 + 1];
                v.z += bl[g * 4 + 2]; v.w += bl[g * 4 + 3];
                d[g] = pk4(v);
            }
            cur = out;
        } else {
            const float* bl = biasC + 7 * 64;
            float* gout = g_G + (size_t)(t0 + tid) * 64;
#pragma unroll
            for (int g = 0; g < 16; g++) {
                float4 v;
                int c = g * 4;
                v.x = gelu_exact(Cf[tid * LDC + c]     + bl[c]     + __bfloat162float(A0[tid * LDA + c]));
                v.y = gelu_exact(Cf[tid * LDC + c + 1] + bl[c + 1] + __bfloat162float(A0[tid * LDA + c + 1]));
                v.z = gelu_exact(Cf[tid * LDC + c + 2] + bl[c + 2] + __bfloat162float(A0[tid * LDA + c + 2]));
                v.w = gelu_exact(Cf[tid * LDC + c + 3] + bl[c + 3] + __bfloat162float(A0[tid * LDA + c + 3]));
                *(float4*)(gout + c) = v;
            }
        }
        __syncthreads();
    }
}

// ---------------------------------------------------------------------------
// K2a: qkv pointwise 64->48, float2-vectorized (unchanged)
// ---------------------------------------------------------------------------
__global__ __launch_bounds__(128) void k_qkv(
    const float* __restrict__ qkv_w, const float* __restrict__ qkv_b)
{
    __shared__ float wq[64 * 48];
    __shared__ float bq[48];
    const int tid = threadIdx.x;
    for (int i = tid; i < 3072; i += 128) {
        int j = i / 64, c = i % 64;
        wq[c * 48 + j] = qkv_w[i];
    }
    if (tid < 48) bq[tid] = qkv_b[tid];
    __syncthreads();

    const int pos = (blockIdx.x * 128 + tid) * 2;
    float2 acc[48];
#pragma unroll
    for (int j = 0; j < 48; j++) { acc[j].x = bq[j]; acc[j].y = bq[j]; }
    for (int c = 0; c < 64; c++) {
        float2 xv = *(const float2*)(g_G + (size_t)c * POSN + pos);
        const float4* wr = (const float4*)(wq + c * 48);
#pragma unroll
        for (int j4 = 0; j4 < 12; j4++) {
            float4 wv = wr[j4];
            acc[j4 * 4 + 0].x += xv.x * wv.x; acc[j4 * 4 + 0].y += xv.y * wv.x;
            acc[j4 * 4 + 1].x += xv.x * wv.y; acc[j4 * 4 + 1].y += xv.y * wv.y;
            acc[j4 * 4 + 2].x += xv.x * wv.z; acc[j4 * 4 + 2].y += xv.y * wv.z;
            acc[j4 * 4 + 3].x += xv.x * wv.w; acc[j4 * 4 + 3].y += xv.y * wv.w;
        }
    }
#pragma unroll
    for (int j = 0; j < 48; j++)
        *(float2*)(g_QKV + (size_t)j * POSN + pos) = acc[j];
}

// ---------------------------------------------------------------------------
// K2b: attention + proj, fused (unchanged)
// ---------------------------------------------------------------------------
#define T_R 260
#define T_CH 780
__global__ __launch_bounds__(256) void k_attn_proj(
    const float* __restrict__ dep1_w, const float* __restrict__ dep_b,
    const float* __restrict__ dep1_b, const float* __restrict__ rpb,
    const float* __restrict__ proj_w, const float* __restrict__ proj_b)
{
    __shared__ float tile[4 * T_CH];
    __shared__ float s_w[162];
    __shared__ float s_b0[18];
    __shared__ float s_b1[18];
    __shared__ float s_r[72];
    __shared__ float wp[16 * 64];
    __shared__ float pb[64];

    const int tid = threadIdx.x;
    if (tid < 162) s_w[tid] = dep1_w[tid];
    if (tid < 18)  s_b0[tid] = dep_b[tid];
    if (tid < 18)  s_b1[tid] = dep1_b[tid];
    if (tid < 72)  s_r[tid] = rpb[tid];
    for (int i = tid; i < 1024; i += 256) {
        int c = i / 16, m = i % 16;
        wp[m * 64 + c] = proj_w[i];
    }
    if (tid < 64) pb[tid] = proj_b[tid];

    const int hh = blockIdx.x >> 3;
    const int w0 = (blockIdx.x & 7) * 256;
    const int pos = hh * 2048 + w0 + tid;
    const int tc = tid + 1;

    float o[16];

    for (int n = 0; n < 8; n++) {
        __syncthreads();
        for (int i = tid; i < 4 * 774; i += 256) {
            int ch = i / 774, rem = i % 774;
            int r = rem / 258, c = rem % 258;
            int hr = hh - 1 + r, wc = w0 - 1 + c;
            float v = 0.f;
            if ((unsigned)hr < 32u && (unsigned)wc < 2048u)
                v = g_QKV[(size_t)(6 * n + 2 + ch) * POSN + hr * 2048 + wc];
            tile[ch * T_CH + r * T_R + c] = v;
        }
        __syncthreads();

        float q0 = g_QKV[(size_t)(6 * n)     * POSN + pos];
        float q1 = g_QKV[(size_t)(6 * n + 1) * POSN + pos];

        float kin[2][9];
#pragma unroll
        for (int d = 0; d < 9; d++) {
            int r = d / 3, dw = d % 3 - 1;
            kin[0][d] = tile[0 * T_CH + r * T_R + tc + dw];
            kin[1][d] = tile[1 * T_CH + r * T_R + tc + dw];
        }
        float lg[9];
#pragma unroll
        for (int s = 0; s < 9; s++) {
            float k0 = kin[0][s], k1 = kin[1][s];
#pragma unroll
            for (int d = 0; d < 9; d++) {
                k0 += s_w[s * 9 + d]       * kin[0][d];
                k1 += s_w[(9 + s) * 9 + d] * kin[1][d];
            }
            k0 += s_b0[s]     + s_b1[s];
            k1 += s_b0[9 + s] + s_b1[9 + s];
            float r = s_r[n * 9 + s];
            lg[s] = SCALE * (q0 * k0 + q1 * k1 + (q0 + q1) * r);
        }
        float mx = lg[0];
#pragma unroll
        for (int s = 1; s < 9; s++) mx = fmaxf(mx, lg[s]);
        float att[9], sum = 0.f;
#pragma unroll
        for (int s = 0; s < 9; s++) { att[s] = __expf(lg[s] - mx); sum += att[s]; }
        float inv = 1.f / sum;

        float vin[2][9];
#pragma unroll
        for (int d = 0; d < 9; d++) {
            int r = d / 3, dw = d % 3 - 1;
            vin[0][d] = tile[2 * T_CH + r * T_R + tc + dw];
            vin[1][d] = tile[3 * T_CH + r * T_R + tc + dw];
        }
        float o0 = 0.f, o1 = 0.f;
#pragma unroll
        for (int s = 0; s < 9; s++) {
            float v0 = vin[0][s], v1 = vin[1][s];
#pragma unroll
            for (int d = 0; d < 9; d++) {
                v0 += s_w[s * 9 + d]       * vin[0][d];
                v1 += s_w[(9 + s) * 9 + d] * vin[1][d];
            }
            v0 += s_b0[s]     + s_b1[s];
            v1 += s_b0[9 + s] + s_b1[9 + s];
            o0 += att[s] * v0;
            o1 += att[s] * v1;
        }
        o[2 * n]     = o0 * inv;
        o[2 * n + 1] = o1 * inv;
    }

#pragma unroll 4
    for (int c = 0; c < 64; c++) {
        float s = pb[c];
#pragma unroll
        for (int m = 0; m < 16; m++) s += o[m] * wp[m * 64 + c];
        g_Pb[(size_t)c * POSN + pos] = __float2bfloat16(s);
    }
}

// ---------------------------------------------------------------------------
// K3: fc2 (64->768) bf16 wmma. NO SMEM C round-trip:
//   acc = load(x tile from gmem)  [residual folded in]
//   acc += ones_A  x bias_B       [bias via one extra MMA]
//   acc += A x B (4 K-steps)
//   store(acc -> y tile, gmem)
// 256 tokens/CTA, 8 warps, 256 CTAs. One sync per chunk (B staging only).
// SMEM: Abuf bf16[256][80] 40960 @0 ; Bb0 8192 @40960 ; Bb1 8192 @49152 ;
//       ones 512 @57344 ; bias tiles 2x2048 @57856  -> total 61952
// ---------------------------------------------------------------------------
__global__ __launch_bounds__(256, 2) void k3_mma(
    const float* __restrict__ x, const float* __restrict__ fc2_w,
    const float* __restrict__ fc2_b, float* __restrict__ y)
{
    extern __shared__ char sm[];
    __nv_bfloat16* Abuf  = (__nv_bfloat16*)sm;
    __nv_bfloat16* Bb0   = (__nv_bfloat16*)(sm + 40960);
    __nv_bfloat16* Bb1   = (__nv_bfloat16*)(sm + 49152);
    __nv_bfloat16* Bones = (__nv_bfloat16*)(sm + 57344);   // 16x16 row-major, col0 = 1
    __nv_bfloat16* Bbi0  = (__nv_bfloat16*)(sm + 57856);   // 4 col-major 16x16 tiles
    __nv_bfloat16* Bbi1  = (__nv_bfloat16*)(sm + 59904);

    const int tid = threadIdx.x;
    const int wid = tid >> 5;
    const int t0  = blockIdx.x * 256;
    const int m0  = wid * 32;

    uint4 bp[2];
    float bnext = 0.f;

    // init ones tile + zero bias tiles
    {
        int r = tid >> 4, c = tid & 15;
        Bones[r * 16 + c] = __float2bfloat16(c == 0 ? 1.f : 0.f);
        ((uint4*)Bbi0)[tid & 127] = make_uint4(0, 0, 0, 0);  // 128 uint4 = 2048B
        ((uint4*)Bbi1)[tid & 127] = make_uint4(0, 0, 0, 0);
    }

    // stage A (bf16 rows from g_Pb), first B chunk, first bias
    {
        const uint4* s = (const uint4*)(g_Pb + (size_t)(t0 + tid) * 64);
        uint4* d = (uint4*)(Abuf + tid * LDA);
#pragma unroll
        for (int g = 0; g < 8; g++) d[g] = s[g];
    }
#pragma unroll
    for (int g = 0; g < 2; g++) {
        int cc = tid + g * 256, n = cc >> 3, k0 = (cc & 7) * 8;
        bp[g] = pk8(fc2_w + (size_t)n * 64 + k0);
    }
#pragma unroll
    for (int g = 0; g < 2; g++) ((uint4*)Bb0)[tid + g * 256] = bp[g];
    if (tid < 64)
        Bbi0[(tid >> 4) * 256 + (tid & 15) * 16] = __float2bfloat16(fc2_b[tid]);
    __syncthreads();

    FragA af[2][4];
    FragA ones_f;
    wmma::load_matrix_sync(ones_f, Bones, 16);
#pragma unroll
    for (int mf = 0; mf < 2; mf++)
#pragma unroll
        for (int ks = 0; ks < 4; ks++)
            wmma::load_matrix_sync(af[mf][ks], Abuf + (m0 + mf * 16) * LDA + ks * 16, LDA);

    for (int nb = 0; nb < 12; nb++) {
        __nv_bfloat16* Bcur  = (nb & 1) ? Bb1 : Bb0;
        __nv_bfloat16* Bnxt  = (nb & 1) ? Bb0 : Bb1;
        __nv_bfloat16* BbiC  = (nb & 1) ? Bbi1 : Bbi0;
        __nv_bfloat16* BbiN  = (nb & 1) ? Bbi0 : Bbi1;

        if (nb < 11) {
#pragma unroll
            for (int g = 0; g < 2; g++) {
                int cc = tid + g * 256, n = cc >> 3, k0 = (cc & 7) * 8;
                bp[g] = pk8(fc2_w + (size_t)((nb + 1) * 64 + n) * 64 + k0);
            }
            if (tid < 64) bnext = fc2_b[(nb + 1) * 64 + tid];
        }

#pragma unroll
        for (int nf = 0; nf < 4; nf++) {
            FragB biasf;
            wmma::load_matrix_sync(biasf, BbiC + nf * 256, 16);
            FragB bf[4];
#pragma unroll
            for (int ks = 0; ks < 4; ks++)
                wmma::load_matrix_sync(bf[ks], Bcur + nf * 16 * 64 + ks * 16, 64);
#pragma unroll
            for (int mf = 0; mf < 2; mf++) {
                FragC acc;
                const size_t base = (size_t)(t0 + m0 + mf * 16) * 768 + nb * 64 + nf * 16;
                wmma::load_matrix_sync(acc, x + base, 768, wmma::mem_row_major);
                wmma::mma_sync(acc, ones_f, biasf, acc);
#pragma unroll
                for (int ks = 0; ks < 4; ks++)
                    wmma::mma_sync(acc, af[mf][ks], bf[ks], acc);
                wmma::store_matrix_sync(y + base, acc, 768, wmma::mem_row_major);
            }
        }

        if (nb < 11) {
#pragma unroll
            for (int g = 0; g < 2; g++) ((uint4*)Bnxt)[tid + g * 256] = bp[g];
            if (tid < 64)
                BbiN[(tid >> 4) * 256 + (tid & 15) * 16] = __float2bfloat16(bnext);
            __syncthreads();
        }
    }
}

// ---------------------------------------------------------------------------
extern "C" void kernel_launch(void* const* d_in, const int* in_sizes, int n_in,
                              void* d_out, int out_size)
{
    const float* x      = (const float*)d_in[0];
    const float* fc1_w  = (const float*)d_in[1];
    const float* fc1_b  = (const float*)d_in[2];
    const float* conv_w = (const float*)d_in[3];
    const float* conv_b = (const float*)d_in[4];
    const float* qkv_w  = (const float*)d_in[5];
    const float* qkv_b  = (const float*)d_in[6];
    const float* dep1_w = (const float*)d_in[7];
    const float* dep_b  = (const float*)d_in[8];
    const float* dep1_b = (const float*)d_in[9];
    const float* rpb    = (const float*)d_in[10];
    const float* proj_w = (const float*)d_in[11];
    const float* proj_b = (const float*)d_in[12];
    const float* fc2_w  = (const float*)d_in[13];
    const float* fc2_b  = (const float*)d_in[14];
    float* y = (float*)d_out;

    cudaFuncSetAttribute(k1_mma, cudaFuncAttributeMaxDynamicSharedMemorySize, 96512);
    cudaFuncSetAttribute(k3_mma, cudaFuncAttributeMaxDynamicSharedMemorySize, 61952);

    k1_mma<<<512, 128, 96512>>>(x, fc1_w, fc1_b, conv_w, conv_b);
    k_qkv <<<256, 128>>>(qkv_w, qkv_b);
    k_attn_proj<<<256, 256>>>(dep1_w, dep_b, dep1_b, rpb, proj_w, proj_b);
    k3_mma<<<256, 256, 61952>>>(x, fc2_w, fc2_b, y);
}